// round 1
// baseline (speedup 1.0000x reference)
#include <cuda_runtime.h>
#include <math.h>

// Problem constants (from reference setup_inputs)
#define BATCH   16
#define NQ      2048
#define NK      2048
#define DIM     64
#define BQ      128     // query rows per block (1 per thread)
#define TILE_K  64      // keys per smem tile
#define CHUNK   16      // keys per online-softmax chunk
#define THREADS 128

__device__ __forceinline__ float ex2_approx(float x) {
    float y;
    asm("ex2.approx.ftz.f32 %0, %1;" : "=f"(y) : "f"(x));
    return y;
}

__global__ __launch_bounds__(THREADS)
void attn_fwd_kernel(const float* __restrict__ Q,
                     const float* __restrict__ K,
                     const float* __restrict__ V,
                     const int* __restrict__ valid_lens,
                     float* __restrict__ Out)
{
    __shared__ float Ks[TILE_K][DIM];
    __shared__ float Vs[TILE_K][DIM];

    const int b  = blockIdx.y;
    const int qi = blockIdx.x * BQ + threadIdx.x;   // this thread's query row
    const int t  = threadIdx.x;

    const int valid = valid_lens[b];                // >= 1 guaranteed

    // Load this thread's query row, folding in (1/sqrt(d)) * log2(e) so the
    // whole softmax runs in log2 space with ex2.approx.
    const float SCALE = 0.125f * 1.44269504088896340736f;
    const float4* qrow = reinterpret_cast<const float4*>(Q + ((size_t)b * NQ + qi) * DIM);
    float4 qreg[DIM / 4];
#pragma unroll
    for (int i = 0; i < DIM / 4; i++) {
        float4 x = qrow[i];
        x.x *= SCALE; x.y *= SCALE; x.z *= SCALE; x.w *= SCALE;
        qreg[i] = x;
    }

    float m = -1e30f;      // running max (log2 units)
    float l = 0.0f;        // running denom
    float o[DIM];
#pragma unroll
    for (int i = 0; i < DIM; i++) o[i] = 0.0f;

    const int ntiles = (valid + TILE_K - 1) / TILE_K;
    const float4* kbase4 = reinterpret_cast<const float4*>(K + (size_t)b * NK * DIM);
    const float4* vbase4 = reinterpret_cast<const float4*>(V + (size_t)b * NK * DIM);

    for (int tile = 0; tile < ntiles; tile++) {
        const int kbase = tile * TILE_K;

        __syncthreads();   // protect smem reuse from previous iteration
        // Cooperative tile load: 64x64 floats = 1024 float4 -> 8 per thread, coalesced.
        const float4* kg = kbase4 + (size_t)kbase * (DIM / 4);
        const float4* vg = vbase4 + (size_t)kbase * (DIM / 4);
        float4* ks4 = reinterpret_cast<float4*>(&Ks[0][0]);
        float4* vs4 = reinterpret_cast<float4*>(&Vs[0][0]);
#pragma unroll
        for (int i = 0; i < (TILE_K * DIM / 4) / THREADS; i++) {
            ks4[t + i * THREADS] = kg[t + i * THREADS];
            vs4[t + i * THREADS] = vg[t + i * THREADS];
        }
        __syncthreads();

        const int kvalid = valid - kbase;   // # valid keys in this tile (>=1)

#pragma unroll
        for (int c = 0; c < TILE_K / CHUNK; c++) {
            const int cbase = c * CHUNK;
            if (cbase >= kvalid) break;     // fully-masked chunk: skip

            // ---- S = q . K^T for 16 keys (16 independent FMA chains) ----
            float s[CHUNK];
#pragma unroll
            for (int j = 0; j < CHUNK; j++) s[j] = 0.0f;
#pragma unroll
            for (int dd = 0; dd < DIM / 4; dd++) {
                const float4 qv = qreg[dd];
#pragma unroll
                for (int j = 0; j < CHUNK; j++) {
                    const float4 kv =
                        reinterpret_cast<const float4*>(&Ks[cbase + j][0])[dd];
                    s[j] = fmaf(qv.x, kv.x, s[j]);
                    s[j] = fmaf(qv.y, kv.y, s[j]);
                    s[j] = fmaf(qv.z, kv.z, s[j]);
                    s[j] = fmaf(qv.w, kv.w, s[j]);
                }
            }

            // ---- mask tail keys + chunk max ----
            float cmax = -1e30f;
#pragma unroll
            for (int j = 0; j < CHUNK; j++) {
                if (cbase + j >= kvalid) s[j] = -1e30f;
                cmax = fmaxf(cmax, s[j]);
            }

            // ---- online softmax update ----
            const float mnew = fmaxf(m, cmax);
            const float corr = ex2_approx(m - mnew);   // 0 when m == -1e30
            m = mnew;
            l *= corr;

            float p[CHUNK];
#pragma unroll
            for (int j = 0; j < CHUNK; j++) {
                p[j] = ex2_approx(s[j] - m);           // exact 0 for masked keys
                l += p[j];
            }

#pragma unroll
            for (int i = 0; i < DIM; i++) o[i] *= corr;

            // ---- O += P @ V ----
#pragma unroll
            for (int j = 0; j < CHUNK; j++) {
                const float pj = p[j];
#pragma unroll
                for (int dd = 0; dd < DIM / 4; dd++) {
                    const float4 vv =
                        reinterpret_cast<const float4*>(&Vs[cbase + j][0])[dd];
                    o[dd * 4 + 0] = fmaf(pj, vv.x, o[dd * 4 + 0]);
                    o[dd * 4 + 1] = fmaf(pj, vv.y, o[dd * 4 + 1]);
                    o[dd * 4 + 2] = fmaf(pj, vv.z, o[dd * 4 + 2]);
                    o[dd * 4 + 3] = fmaf(pj, vv.w, o[dd * 4 + 3]);
                }
            }
        }
    }

    const float inv = 1.0f / l;
    float4* orow = reinterpret_cast<float4*>(Out + ((size_t)b * NQ + qi) * DIM);
#pragma unroll
    for (int dd = 0; dd < DIM / 4; dd++) {
        float4 r;
        r.x = o[dd * 4 + 0] * inv;
        r.y = o[dd * 4 + 1] * inv;
        r.z = o[dd * 4 + 2] * inv;
        r.w = o[dd * 4 + 3] * inv;
        orow[dd] = r;
    }
}

extern "C" void kernel_launch(void* const* d_in, const int* in_sizes, int n_in,
                              void* d_out, int out_size) {
    const float* Q = (const float*)d_in[0];
    const float* K = (const float*)d_in[1];
    const float* V = (const float*)d_in[2];
    const int* valid_lens = (const int*)d_in[3];
    float* Out = (float*)d_out;

    dim3 grid(NQ / BQ, BATCH);   // 16 x 16 = 256 CTAs
    attn_fwd_kernel<<<grid, THREADS>>>(Q, K, V, valid_lens, Out);
}

// round 3
// speedup vs baseline: 7.1640x; 7.1640x over previous
#include <cuda_runtime.h>
#include <cstdint>

// ---------------- problem constants ----------------
#define BATCH   16
#define NQ      2048
#define NK      2048
#define DIM     64
#define BQ      64      // queries per CTA (16 per warp)
#define TK      64      // keys per tile
#define THREADS 128

// ---------------- smem layout (float offsets) ----------------
#define KP 68           // K tile pitch (floats)  -> conflict-free B-frag reads
#define VP 72           // V tile pitch (floats)
#define PP 68           // P / Q-staging pitch
#define KS_OFF(buf) ((buf) * (TK * KP))
#define VS_BASE     (2 * TK * KP)
#define VS_OFF(buf) (VS_BASE + (buf) * (TK * VP))
#define PS_OFF      (VS_BASE + 2 * TK * VP)
#define SMEM_FLOATS (PS_OFF + BQ * PP)
#define SMEM_BYTES  (SMEM_FLOATS * 4)

// ---------------- helpers ----------------
__device__ __forceinline__ uint32_t smem_u32(const void* p) {
    uint32_t a;
    asm("{ .reg .u64 t; cvta.to.shared.u64 t, %1; cvt.u32.u64 %0, t; }" : "=r"(a) : "l"(p));
    return a;
}
__device__ __forceinline__ float ex2f(float x) {
    float y; asm("ex2.approx.ftz.f32 %0, %1;" : "=f"(y) : "f"(x)); return y;
}
__device__ __forceinline__ uint32_t f2tf32(float x) {
    uint32_t u; asm("cvt.rna.tf32.f32 %0, %1;" : "=r"(u) : "f"(x)); return u;
}
__device__ __forceinline__ void cpa16(uint32_t dst, const float* src) {
    asm volatile("cp.async.cg.shared.global [%0], [%1], 16;" :: "r"(dst), "l"(src) : "memory");
}
__device__ __forceinline__ void mma8(float c[4], const uint32_t a[4], uint32_t b0, uint32_t b1) {
    asm volatile(
        "mma.sync.aligned.m16n8k8.row.col.f32.tf32.tf32.f32 "
        "{%0,%1,%2,%3}, {%4,%5,%6,%7}, {%8,%9}, {%0,%1,%2,%3};"
        : "+f"(c[0]), "+f"(c[1]), "+f"(c[2]), "+f"(c[3])
        : "r"(a[0]), "r"(a[1]), "r"(a[2]), "r"(a[3]), "r"(b0), "r"(b1));
}

// ---------------- kernel ----------------
__global__ __launch_bounds__(THREADS)
void attn_mma_kernel(const float* __restrict__ Q,
                     const float* __restrict__ K,
                     const float* __restrict__ V,
                     const int* __restrict__ valid_lens,
                     float* __restrict__ Out)
{
    extern __shared__ float sm[];
    const uint32_t sb = smem_u32(sm);
    const uint32_t* su = reinterpret_cast<const uint32_t*>(sm);

    const int t    = threadIdx.x;
    const int w    = t >> 5;
    const int lane = t & 31;
    const int g    = lane >> 2;     // group id (row within fragment)
    const int tq   = lane & 3;      // thread in group (col within fragment)
    const int b    = blockIdx.y;
    const int qbase = blockIdx.x * BQ;

    const int valid  = valid_lens[b];
    const int ntiles = (valid + TK - 1) / TK;

    const float* Kg = K + (size_t)b * NK * DIM;
    const float* Vg = V + (size_t)b * NK * DIM;

    // ---- issue cp.async for one K/V tile into buffer buf ----
    auto issue = [&](int tile, int buf) {
#pragma unroll
        for (int i = 0; i < 8; i++) {
            const int c = t + 128 * i;                 // 0..1023 chunk id
            const int row = c >> 4, seg = c & 15;
            cpa16(sb + (uint32_t)(KS_OFF(buf) + row * KP + seg * 4) * 4,
                  Kg + (size_t)(tile * TK + row) * DIM + seg * 4);
        }
#pragma unroll
        for (int i = 0; i < 8; i++) {
            const int c = t + 128 * i;
            const int row = c >> 4, seg = c & 15;
            cpa16(sb + (uint32_t)(VS_OFF(buf) + row * VP + seg * 4) * 4,
                  Vg + (size_t)(tile * TK + row) * DIM + seg * 4);
        }
        asm volatile("cp.async.commit_group;" ::: "memory");
    };

    issue(0, 0);   // overlap tile-0 load with Q staging

    // ---- stage Q (scaled, tf32-rounded) through the P smem region ----
    {
        const float SCALE = 0.125f * 1.44269504088896340736f;  // (1/sqrt(64))*log2(e)
        const float4* Qg4 = reinterpret_cast<const float4*>(Q + ((size_t)b * NQ + qbase) * DIM);
#pragma unroll
        for (int i = 0; i < 8; i++) {
            const int c = t + 128 * i;
            const int row = c >> 4, seg = c & 15;
            float4 v = Qg4[row * 16 + seg];
            uint4 u;
            u.x = f2tf32(v.x * SCALE); u.y = f2tf32(v.y * SCALE);
            u.z = f2tf32(v.z * SCALE); u.w = f2tf32(v.w * SCALE);
            *reinterpret_cast<uint4*>(&sm[PS_OFF + row * PP + seg * 4]) = u;
        }
    }
    __syncthreads();

    // ---- load Q fragments (A of m16n8k8): qa[kb] covers dims kb*8..kb*8+7 ----
    uint32_t qa[8][4];
    const int pr0 = PS_OFF + (w * 16 + g) * PP;   // this thread's P row (row g)
    const int pr1 = pr0 + 8 * PP;                 // row g+8
    {
        const int r0 = pr0 + tq, r1 = pr1 + tq;
#pragma unroll
        for (int kb = 0; kb < 8; kb++) {
            qa[kb][0] = su[r0 + kb * 8];
            qa[kb][1] = su[r1 + kb * 8];
            qa[kb][2] = su[r0 + kb * 8 + 4];
            qa[kb][3] = su[r1 + kb * 8 + 4];
        }
    }

    float oc[8][4];
#pragma unroll
    for (int nb = 0; nb < 8; nb++) { oc[nb][0] = oc[nb][1] = oc[nb][2] = oc[nb][3] = 0.0f; }
    float l0 = 0.0f, l1 = 0.0f;

    for (int tile = 0; tile < ntiles; tile++) {
        const int buf = tile & 1;
        if (tile + 1 < ntiles) {
            issue(tile + 1, buf ^ 1);
            asm volatile("cp.async.wait_group 1;" ::: "memory");
        } else {
            asm volatile("cp.async.wait_group 0;" ::: "memory");
        }
        __syncthreads();   // tile `buf` visible to all, previous compute done

        const int kbase = tile * TK;

        // ---- GEMM1: S[16q x 64k] = Q x K^T, fused softmax, P -> smem ----
        const uint32_t* ku = su + KS_OFF(buf);
#pragma unroll
        for (int nb = 0; nb < 8; nb++) {
            float c[4] = {0.f, 0.f, 0.f, 0.f};
            const int kb_base = (nb * 8 + g) * KP + tq;
#pragma unroll
            for (int kb = 0; kb < 8; kb++) {
                const uint32_t b0 = ku[kb_base + kb * 8];
                const uint32_t b1 = ku[kb_base + kb * 8 + 4];
                mma8(c, qa[kb], b0, b1);
            }
            const int col = kbase + nb * 8 + 2 * tq;
            float p0 = ex2f(c[0]), p1 = ex2f(c[1]), p2 = ex2f(c[2]), p3 = ex2f(c[3]);
            if (col     >= valid) { p0 = 0.f; p2 = 0.f; }
            if (col + 1 >= valid) { p1 = 0.f; p3 = 0.f; }
            l0 += p0 + p1;
            l1 += p2 + p3;
            uint2 s0, s1;
            s0.x = f2tf32(p0); s0.y = f2tf32(p1);
            s1.x = f2tf32(p2); s1.y = f2tf32(p3);
            *reinterpret_cast<uint2*>(&sm[pr0 + nb * 8 + 2 * tq]) = s0;
            *reinterpret_cast<uint2*>(&sm[pr1 + nb * 8 + 2 * tq]) = s1;
        }
        __syncwarp();   // P region is per-warp; order STS -> LDS across lanes

        // ---- GEMM2: O[16q x 64d] += P x V ----
        const float* vf = sm + VS_OFF(buf);
#pragma unroll
        for (int kb = 0; kb < 8; kb++) {
            uint32_t a[4];
            const int pa = pr0 + kb * 8 + tq;
            a[0] = su[pa];
            a[1] = su[pa + 8 * PP];
            a[2] = su[pa + 4];
            a[3] = su[pa + 8 * PP + 4];
            const int vb = (kb * 8 + tq) * VP + g;
#pragma unroll
            for (int nb = 0; nb < 8; nb++) {
                const uint32_t b0 = f2tf32(vf[vb + nb * 8]);
                const uint32_t b1 = f2tf32(vf[vb + 4 * VP + nb * 8]);
                mma8(oc[nb], a, b0, b1);
            }
        }
        __syncthreads();   // all warps done with buf before it is refilled
    }

    // ---- finalize: quad-reduce row sums, normalize, store ----
    l0 += __shfl_xor_sync(0xffffffffu, l0, 1);
    l0 += __shfl_xor_sync(0xffffffffu, l0, 2);
    l1 += __shfl_xor_sync(0xffffffffu, l1, 1);
    l1 += __shfl_xor_sync(0xffffffffu, l1, 2);
    const float inv0 = 1.0f / l0;
    const float inv1 = 1.0f / l1;

    float* Og = Out + ((size_t)b * NQ + qbase + w * 16) * DIM;
#pragma unroll
    for (int nb = 0; nb < 8; nb++) {
        float2 v0, v1;
        v0.x = oc[nb][0] * inv0; v0.y = oc[nb][1] * inv0;
        v1.x = oc[nb][2] * inv1; v1.y = oc[nb][3] * inv1;
        *reinterpret_cast<float2*>(Og + (size_t)g * DIM + nb * 8 + 2 * tq) = v0;
        *reinterpret_cast<float2*>(Og + (size_t)(g + 8) * DIM + nb * 8 + 2 * tq) = v1;
    }
}

extern "C" void kernel_launch(void* const* d_in, const int* in_sizes, int n_in,
                              void* d_out, int out_size) {
    const float* Q = (const float*)d_in[0];
    const float* K = (const float*)d_in[1];
    const float* V = (const float*)d_in[2];
    const int* valid_lens = (const int*)d_in[3];
    float* Out = (float*)d_out;

    cudaFuncSetAttribute(attn_mma_kernel, cudaFuncAttributeMaxDynamicSharedMemorySize, SMEM_BYTES);
    dim3 grid(NQ / BQ, BATCH);   // 32 x 16 = 512 CTAs
    attn_mma_kernel<<<grid, THREADS, SMEM_BYTES>>>(Q, K, V, valid_lens, Out);
}

// round 5
// speedup vs baseline: 11.6672x; 1.6286x over previous
#include <cuda_runtime.h>
#include <cstdint>

// ---------------- problem constants ----------------
#define BATCH   16
#define NQ      2048
#define NK      2048
#define DIM     64
#define BQ      128     // queries per CTA (32 per warp)
#define TK      64      // keys per tile
#define KCH_TILES 8     // tiles per k-chunk (512 keys)
#define THREADS 128

// ---------------- smem layout (float offsets) ----------------
#define KP 68           // K tile pitch (floats)
#define VP 72           // V tile pitch (floats)
#define PP 68           // P / Q-staging pitch
#define KS_OFF(buf) ((buf) * (TK * KP))
#define VS_BASE     (2 * TK * KP)
#define VS_OFF(buf) (VS_BASE + (buf) * (TK * VP))
#define PS_OFF      (VS_BASE + 2 * TK * VP)
#define SMEM_FLOATS (PS_OFF + BQ * PP)
#define SMEM_BYTES  (SMEM_FLOATS * 4)          // 106,496 B -> 2 CTAs/SM

// ---------------- scratch (allocation-free) ----------------
__device__ float g_lsum[BATCH * NQ];

// ---------------- helpers ----------------
__device__ __forceinline__ uint32_t smem_u32(const void* p) {
    uint32_t a;
    asm("{ .reg .u64 t; cvta.to.shared.u64 t, %1; cvt.u32.u64 %0, t; }" : "=r"(a) : "l"(p));
    return a;
}
__device__ __forceinline__ float ex2f(float x) {
    float y; asm("ex2.approx.ftz.f32 %0, %1;" : "=f"(y) : "f"(x)); return y;
}
__device__ __forceinline__ uint32_t f2tf32(float x) {
    uint32_t u; asm("cvt.rna.tf32.f32 %0, %1;" : "=r"(u) : "f"(x)); return u;
}
__device__ __forceinline__ void cpa16(uint32_t dst, const float* src) {
    asm volatile("cp.async.cg.shared.global [%0], [%1], 16;" :: "r"(dst), "l"(src) : "memory");
}
__device__ __forceinline__ void mma8(float c[4], const uint32_t a[4], uint32_t b0, uint32_t b1) {
    asm volatile(
        "mma.sync.aligned.m16n8k8.row.col.f32.tf32.tf32.f32 "
        "{%0,%1,%2,%3}, {%4,%5,%6,%7}, {%8,%9}, {%0,%1,%2,%3};"
        : "+f"(c[0]), "+f"(c[1]), "+f"(c[2]), "+f"(c[3])
        : "r"(a[0]), "r"(a[1]), "r"(a[2]), "r"(a[3]), "r"(b0), "r"(b1));
}

// ---------------- zero-init kernel ----------------
__global__ void zero_kernel(float* __restrict__ out) {
    const int stride = gridDim.x * blockDim.x;
    int i = blockIdx.x * blockDim.x + threadIdx.x;
    float4 z = {0.f, 0.f, 0.f, 0.f};
    float4* o4 = reinterpret_cast<float4*>(out);
    for (int idx = i; idx < BATCH * NQ * DIM / 4; idx += stride) o4[idx] = z;
    float4* l4 = reinterpret_cast<float4*>(g_lsum);
    for (int idx = i; idx < BATCH * NQ / 4; idx += stride) l4[idx] = z;
}

// ---------------- normalize kernel ----------------
__global__ void norm_kernel(float* __restrict__ out) {
    const int i = blockIdx.x * blockDim.x + threadIdx.x;   // one float4 per thread
    float4 v = reinterpret_cast<float4*>(out)[i];
    const float inv = 1.0f / g_lsum[i >> 4];               // 16 float4 per q-row
    v.x *= inv; v.y *= inv; v.z *= inv; v.w *= inv;
    reinterpret_cast<float4*>(out)[i] = v;
}

// ---------------- main kernel ----------------
__global__ __launch_bounds__(THREADS)
void attn_mma_kernel(const float* __restrict__ Q,
                     const float* __restrict__ K,
                     const float* __restrict__ V,
                     const int* __restrict__ valid_lens,
                     float* __restrict__ Out)
{
    extern __shared__ float sm[];
    const uint32_t sb = smem_u32(sm);
    const uint32_t* su = reinterpret_cast<const uint32_t*>(sm);

    const int t    = threadIdx.x;
    const int w    = t >> 5;
    const int lane = t & 31;
    const int g    = lane >> 2;
    const int tq   = lane & 3;
    const int b    = blockIdx.y;
    const int qbase = blockIdx.x * BQ;
    const int kc   = blockIdx.z;

    const int valid  = valid_lens[b];
    const int ntiles = (valid + TK - 1) / TK;
    const int t0 = kc * KCH_TILES;
    if (t0 >= ntiles) return;                       // this k-chunk is fully masked
    const int t1 = min(t0 + KCH_TILES, ntiles);

    const float* Kg = K + (size_t)b * NK * DIM;
    const float* Vg = V + (size_t)b * NK * DIM;

    auto issue = [&](int tile, int buf) {
#pragma unroll
        for (int i = 0; i < 8; i++) {
            const int c = t + 128 * i;              // 0..1023
            const int row = c >> 4, seg = c & 15;
            cpa16(sb + (uint32_t)(KS_OFF(buf) + row * KP + seg * 4) * 4,
                  Kg + (size_t)(tile * TK + row) * DIM + seg * 4);
        }
#pragma unroll
        for (int i = 0; i < 8; i++) {
            const int c = t + 128 * i;
            const int row = c >> 4, seg = c & 15;
            cpa16(sb + (uint32_t)(VS_OFF(buf) + row * VP + seg * 4) * 4,
                  Vg + (size_t)(tile * TK + row) * DIM + seg * 4);
        }
        asm volatile("cp.async.commit_group;" ::: "memory");
    };

    issue(t0, 0);

    // ---- stage Q (scaled, tf32) through P region: 128 rows x 64 ----
    {
        const float SCALE = 0.125f * 1.44269504088896340736f;
        const float4* Qg4 = reinterpret_cast<const float4*>(Q + ((size_t)b * NQ + qbase) * DIM);
#pragma unroll
        for (int i = 0; i < 16; i++) {
            const int c = t + 128 * i;              // 0..2047
            const int row = c >> 4, seg = c & 15;
            float4 v = Qg4[row * 16 + seg];
            uint4 u;
            u.x = f2tf32(v.x * SCALE); u.y = f2tf32(v.y * SCALE);
            u.z = f2tf32(v.z * SCALE); u.w = f2tf32(v.w * SCALE);
            *reinterpret_cast<uint4*>(&sm[PS_OFF + row * PP + seg * 4]) = u;
        }
    }
    __syncthreads();

    // ---- Q fragments: 2 M-blocks of 16 rows each ----
    uint32_t qa[2][8][4];
    const int wrow = PS_OFF + (w * 32 + g) * PP;    // row g of this warp's block
#pragma unroll
    for (int f = 0; f < 2; f++) {
        const int r0 = wrow + f * 16 * PP + tq;
        const int r1 = r0 + 8 * PP;
#pragma unroll
        for (int kb = 0; kb < 8; kb++) {
            qa[f][kb][0] = su[r0 + kb * 8];
            qa[f][kb][1] = su[r1 + kb * 8];
            qa[f][kb][2] = su[r0 + kb * 8 + 4];
            qa[f][kb][3] = su[r1 + kb * 8 + 4];
        }
    }

    float oc[2][8][4];
#pragma unroll
    for (int f = 0; f < 2; f++)
#pragma unroll
        for (int nb = 0; nb < 8; nb++)
            oc[f][nb][0] = oc[f][nb][1] = oc[f][nb][2] = oc[f][nb][3] = 0.0f;
    float lr[4] = {0.f, 0.f, 0.f, 0.f};             // rows g, g+8, g+16, g+24

    for (int tt = t0; tt < t1; tt++) {
        const int buf = (tt - t0) & 1;
        if (tt + 1 < t1) {
            issue(tt + 1, buf ^ 1);
            asm volatile("cp.async.wait_group 1;" ::: "memory");
        } else {
            asm volatile("cp.async.wait_group 0;" ::: "memory");
        }
        __syncthreads();                             // tile `buf` visible to all warps

        // ---- pre-convert V tile to tf32 in place ----
        {
            float* vf = sm + VS_OFF(buf);
#pragma unroll
            for (int i = 0; i < 8; i++) {
                const int c = t + 128 * i;
                const int row = c >> 4, seg = c & 15;
                float4 v = *reinterpret_cast<float4*>(&vf[row * VP + seg * 4]);
                uint4 u;
                u.x = f2tf32(v.x); u.y = f2tf32(v.y);
                u.z = f2tf32(v.z); u.w = f2tf32(v.w);
                *reinterpret_cast<uint4*>(&vf[row * VP + seg * 4]) = u;
            }
        }

        const int kbase = tt * TK;

        // ---- GEMM1: S[32q x 64k] + softmax + P -> smem ----
        const uint32_t* ku = su + KS_OFF(buf);
#pragma unroll
        for (int nb = 0; nb < 8; nb++) {
            float c0[4] = {0.f, 0.f, 0.f, 0.f};
            float c1[4] = {0.f, 0.f, 0.f, 0.f};
            const int kb_base = (nb * 8 + g) * KP + tq;
#pragma unroll
            for (int kb = 0; kb < 8; kb++) {
                const uint32_t b0 = ku[kb_base + kb * 8];
                const uint32_t b1 = ku[kb_base + kb * 8 + 4];
                mma8(c0, qa[0][kb], b0, b1);
                mma8(c1, qa[1][kb], b0, b1);
            }
            const int col = kbase + nb * 8 + 2 * tq;
            const bool m0 = (col >= valid), m1 = (col + 1 >= valid);

            float p00 = ex2f(c0[0]), p01 = ex2f(c0[1]), p02 = ex2f(c0[2]), p03 = ex2f(c0[3]);
            float p10 = ex2f(c1[0]), p11 = ex2f(c1[1]), p12 = ex2f(c1[2]), p13 = ex2f(c1[3]);
            if (m0) { p00 = 0.f; p02 = 0.f; p10 = 0.f; p12 = 0.f; }
            if (m1) { p01 = 0.f; p03 = 0.f; p11 = 0.f; p13 = 0.f; }

            uint2 s00, s01, s10, s11;
            s00.x = f2tf32(p00); s00.y = f2tf32(p01);
            s01.x = f2tf32(p02); s01.y = f2tf32(p03);
            s10.x = f2tf32(p10); s10.y = f2tf32(p11);
            s11.x = f2tf32(p12); s11.y = f2tf32(p13);
            lr[0] += __uint_as_float(s00.x) + __uint_as_float(s00.y);
            lr[1] += __uint_as_float(s01.x) + __uint_as_float(s01.y);
            lr[2] += __uint_as_float(s10.x) + __uint_as_float(s10.y);
            lr[3] += __uint_as_float(s11.x) + __uint_as_float(s11.y);

            const int pc = nb * 8 + 2 * tq;
            *reinterpret_cast<uint2*>(&sm[wrow + pc]) = s00;
            *reinterpret_cast<uint2*>(&sm[wrow + 8 * PP + pc]) = s01;
            *reinterpret_cast<uint2*>(&sm[wrow + 16 * PP + pc]) = s10;
            *reinterpret_cast<uint2*>(&sm[wrow + 24 * PP + pc]) = s11;
        }
        __syncthreads();                             // V conversion visible to all

        // ---- GEMM2: O[32q x 64d] += P x V ----
        const uint32_t* vu = su + VS_OFF(buf);
#pragma unroll
        for (int kb = 0; kb < 8; kb++) {
            uint32_t a0[4], a1[4];
            const int pa = wrow + kb * 8 + tq;
            a0[0] = su[pa];
            a0[1] = su[pa + 8 * PP];
            a0[2] = su[pa + 4];
            a0[3] = su[pa + 8 * PP + 4];
            a1[0] = su[pa + 16 * PP];
            a1[1] = su[pa + 24 * PP];
            a1[2] = su[pa + 16 * PP + 4];
            a1[3] = su[pa + 24 * PP + 4];
            const int vb = (kb * 8 + tq) * VP + g;
#pragma unroll
            for (int nb = 0; nb < 8; nb++) {
                const uint32_t b0 = vu[vb + nb * 8];
                const uint32_t b1 = vu[vb + 4 * VP + nb * 8];
                mma8(oc[0][nb], a0, b0, b1);
                mma8(oc[1][nb], a1, b0, b1);
            }
        }
        __syncthreads();   // CRITICAL: all warps done reading buf before next
                           // iteration's issue() overwrites the other buffer
                           // that GEMM2 of the *next* iteration still pairs with.
    }

    // ---- reduce l over quads, add to global sums ----
#pragma unroll
    for (int i = 0; i < 4; i++) {
        lr[i] += __shfl_xor_sync(0xffffffffu, lr[i], 1);
        lr[i] += __shfl_xor_sync(0xffffffffu, lr[i], 2);
    }
    if (tq == 0) {
        const int rbase = b * NQ + qbase + w * 32 + g;
        atomicAdd(&g_lsum[rbase],      lr[0]);
        atomicAdd(&g_lsum[rbase + 8],  lr[1]);
        atomicAdd(&g_lsum[rbase + 16], lr[2]);
        atomicAdd(&g_lsum[rbase + 24], lr[3]);
    }

    // ---- accumulate partial O into gmem ----
    float* Ob = Out + ((size_t)b * NQ + qbase + w * 32) * DIM;
#pragma unroll
    for (int f = 0; f < 2; f++) {
        const int r0 = f * 16 + g;
        const int r1 = r0 + 8;
#pragma unroll
        for (int nb = 0; nb < 8; nb++) {
            const int cc = nb * 8 + 2 * tq;
            atomicAdd(&Ob[(size_t)r0 * DIM + cc],     oc[f][nb][0]);
            atomicAdd(&Ob[(size_t)r0 * DIM + cc + 1], oc[f][nb][1]);
            atomicAdd(&Ob[(size_t)r1 * DIM + cc],     oc[f][nb][2]);
            atomicAdd(&Ob[(size_t)r1 * DIM + cc + 1], oc[f][nb][3]);
        }
    }
}

extern "C" void kernel_launch(void* const* d_in, const int* in_sizes, int n_in,
                              void* d_out, int out_size) {
    const float* Q = (const float*)d_in[0];
    const float* K = (const float*)d_in[1];
    const float* V = (const float*)d_in[2];
    const int* valid_lens = (const int*)d_in[3];
    float* Out = (float*)d_out;

    zero_kernel<<<1024, 256>>>(Out);

    cudaFuncSetAttribute(attn_mma_kernel, cudaFuncAttributeMaxDynamicSharedMemorySize, SMEM_BYTES);
    dim3 grid(NQ / BQ, BATCH, (NK + TK * KCH_TILES - 1) / (TK * KCH_TILES));  // 16 x 16 x 4
    attn_mma_kernel<<<grid, THREADS, SMEM_BYTES>>>(Q, K, V, valid_lens, Out);

    norm_kernel<<<BATCH * NQ * DIM / 4 / 256, 256>>>(Out);
}